// round 16
// baseline (speedup 1.0000x reference)
#include <cuda_runtime.h>
#include <cuda_fp16.h>
#include <math.h>

#define NB 32
#define CH 16
#define G  256
#define GG (G*G)

#define XSTR 40
#define BSTR 40
#define TI   16
#define TH   18
#define RH   20
#define XEL2 (TH*TH*XSTR)
#define BROWS (9*2*32)
#define SMEM_MMA (XEL2*2 + BROWS*BSTR*2)           // 72,000 B
#define SMEM_MMA_C1 (SMEM_MMA + RH*RH*4 + CH*9*8)  // 74,752 B

#define LSTR 258
#define ASCALE 256.0f
#define AINV   (1.0f/256.0f)

typedef unsigned int u32;

// ---------------- scratch ----------------
__device__ float  g_rhat[NB*GG];
__device__ float2 g_c1[NB*GG];
__device__ float2 g_c2[NB*GG];
__device__ __half g_A[(size_t)NB*GG*32];
__device__ __half g_B[(size_t)NB*GG*32];
__device__ __half g_Bw[4*NB*BROWS*32];

// ---------------- helpers ----------------
__device__ __forceinline__ u32 sptr(const void* p) {
    return (u32)__cvta_generic_to_shared(p);
}
__device__ __forceinline__ void ldmat4(u32* r, u32 addr) {
    asm volatile("ldmatrix.sync.aligned.m8n8.x4.shared.b16 {%0,%1,%2,%3}, [%4];"
        : "=r"(r[0]), "=r"(r[1]), "=r"(r[2]), "=r"(r[3]) : "r"(addr));
}
__device__ __forceinline__ void mma_f16(float* d, const u32* a, const u32* b) {
    asm volatile("mma.sync.aligned.m16n8k16.row.col.f32.f16.f16.f32 "
        "{%0,%1,%2,%3}, {%4,%5,%6,%7}, {%8,%9}, {%0,%1,%2,%3};"
        : "+f"(d[0]), "+f"(d[1]), "+f"(d[2]), "+f"(d[3])
        : "r"(a[0]), "r"(a[1]), "r"(a[2]), "r"(a[3]), "r"(b[0]), "r"(b[1]));
}
// pack two floats into fp16x2 (a in lower half)
__device__ __forceinline__ u32 pk16(float a, float b) {
    u32 r;
    asm("cvt.rn.f16x2.f32 %0, %1, %2;" : "=r"(r) : "f"(b), "f"(a));
    return r;
}
__device__ __forceinline__ int Lperm(int n) {
    return ((n & 7) >> 1) * 8 + ((n >> 3) << 1) + (n & 1);
}

// ---------------- twiddle table ----------------
__device__ __forceinline__ void gen_tw(float2* tw, int tid, float dir)
{
    if (tid < 255) {
        int s  = 31 - __clz(tid + 1);
        int jm = tid - ((1 << s) - 1);
        float ang = dir * 3.14159265358979323846f * (float)jm / (float)(1 << s);
        float sn, cs;
        __sincosf(ang, &sn, &cs);
        tw[tid] = make_float2(cs, sn);
    }
}

// ---------------- 256-pt FFT, 8 lines/block ----------------
__device__ __forceinline__ void fft256_multi(float2* s0, float2* s1, int lt, const float2* tw)
{
    float2* src = s0; float2* dst = s1;
#pragma unroll
    for (int s = 0; s < 8; s++) {
        int Ns = 1 << s;
#pragma unroll
        for (int u = 0; u < 4; u++) {
            int j  = lt + 32*u;
            int jm = j & (Ns - 1);
            float2 a = src[j];
            float2 b = src[j + 128];
            float2 w = tw[Ns - 1 + jm];
            float2 bt = make_float2(b.x*w.x - b.y*w.y, b.x*w.y + b.y*w.x);
            int id = ((j >> s) << (s + 1)) | jm;
            dst[id]      = make_float2(a.x + bt.x, a.y + bt.y);
            dst[id + Ns] = make_float2(a.x - bt.x, a.y - bt.y);
        }
        __syncthreads();
        float2* tt = src; src = dst; dst = tt;
    }
}

// ---------------- ifft2 pass A ----------------
__global__ void ifft_passA_kernel(const float* __restrict__ r)
{
    __shared__ float2 sA[8*LSTR], sB[8*LSTR], tw[256];
    const int b = blockIdx.y, tid = threadIdx.x;
    const int line = tid >> 5, lt = tid & 31;
    const int m = blockIdx.x*8 + line;

    gen_tw(tw, tid, +1.0f);

    const bool zrow = (m == 0 || m == 128);
    const float sm = (m < 128) ? 1.f : -1.f;
    const int   im = (m < 128) ? (m - 1) : (255 - m);
    const float* rrow = r + ((size_t)b*127 + (zrow ? 0 : im))*127;

    float2* s0 = sA + line*LSTR;
    float2* s1 = sB + line*LSTR;
#pragma unroll
    for (int u = 0; u < 8; u++) {
        int n = lt + 32*u;
        float v = 0.f;
        if (!zrow && n != 0 && n != 128)
            v = (n < 128) ? rrow[n-1] : -rrow[255-n];
        s0[n] = make_float2(sm * v, 0.f);
    }
    __syncthreads();
    fft256_multi(s0, s1, lt, tw);

    const float sc = 1.0f / 256.0f;
    const int mi = tid & 7, vsub = tid >> 3;
    const int m0 = blockIdx.x*8;
#pragma unroll
    for (int chunk = 0; chunk < 8; chunk++) {
        int v = chunk*32 + vsub;
        float2 val = sA[mi*LSTR + v];
        g_c1[(size_t)b*GG + (size_t)((v+128)&255)*256 + m0 + mi] =
            make_float2(val.x*sc, val.y*sc);
    }
}

// ---------------- ifft2 pass B ----------------
__global__ void ifft_passB_kernel()
{
    __shared__ float2 sA[8*LSTR], sB[8*LSTR], tw[256];
    const int b = blockIdx.y, tid = threadIdx.x;
    const int line = tid >> 5, lt = tid & 31;
    const int vp = blockIdx.x*8 + line;
    const size_t base = (size_t)b*GG + (size_t)vp*256;

    gen_tw(tw, tid, +1.0f);

    float2* s0 = sA + line*LSTR;
    float2* s1 = sB + line*LSTR;
#pragma unroll
    for (int u = 0; u < 8; u++) {
        int n = lt + 32*u;
        s0[n] = g_c1[base + n];
    }
    __syncthreads();
    fft256_multi(s0, s1, lt, tw);

    const float sc = 1.0f / 256.0f;
    const int vi = tid & 7, usub = tid >> 3;
    const int v0 = blockIdx.x*8;
#pragma unroll
    for (int chunk = 0; chunk < 8; chunk++) {
        int uu = chunk*32 + usub;
        g_rhat[(size_t)b*GG + (size_t)((uu+128)&255)*256 + v0 + vi] =
            sA[vi*LSTR + uu].x * sc;
    }
}

// ---------------- weight precompute: fp16 hi/lo, n-permuted ----------------
__global__ void wprep_kernel(const float* __restrict__ w2r, const float* __restrict__ w2i,
                             const float* __restrict__ w3r, const float* __restrict__ w3i)
{
    const int b = blockIdx.x, layer = blockIdx.y, tid = threadIdx.x;
    const float *wr, *wi; bool adj;
    if      (layer == 0) { wr = w2r; wi = w2i; adj = false; }
    else if (layer == 1) { wr = w3r; wi = w3i; adj = false; }
    else if (layer == 2) { wr = w3r; wi = w3i; adj = true;  }
    else                 { wr = w2r; wi = w2i; adj = true;  }
    __half* dst = g_Bw + ((size_t)(layer*NB + b))*BROWS*32;

    for (int idx = tid; idx < 9*32*32; idx += 256) {
        int tap = idx >> 10;
        int n = (idx >> 5) & 31;
        int k = idx & 31;
        int dy = tap/3, dx = tap - 3*dy;
        int cn = Lperm(n);
        int co = cn & 15, ci = k & 15;
        float vr, vi;
        if (!adj) { int off = ((b*CH + co)*CH + ci)*9 + dy*3 + dx; vr = wr[off]; vi = wi[off]; }
        else      { int off = ((b*CH + ci)*CH + co)*9 + dx*3 + dy; vr = wr[off]; vi = -wi[off]; }
        float v = (cn < 16) ? ((k < 16) ? vr : -vi)
                            : ((k < 16) ? vi :  vr);
        __half h = __float2half(v);
        __half l = __float2half(v - __half2float(h));
        dst[((tap*2 + 0)*32 + n)*32 + k] = h;
        dst[((tap*2 + 1)*32 + n)*32 + k] = l;
    }
}

// ---------------- conv16 via mma.sync fp16; C1 fuses conv1 as producer ----------------
template<bool WT, bool C1>
__global__ void __launch_bounds__(256, 2) conv16_mma(
    const __half* __restrict__ in, __half* __restrict__ out,
    const __half* __restrict__ Bw_base, int layer,
    const float* __restrict__ wtr, const float* __restrict__ wti,
    const float* __restrict__ w1r, const float* __restrict__ w1i)
{
    extern __shared__ __half sm[];
    __half* sX = sm;                        // [TH*TH][XSTR] fp16, 32 used
    __half* sB = sm + XEL2;                 // [(tap*2+hl)*32 + n][BSTR]
    float*  sR  = (float*)(sm + XEL2 + BROWS*BSTR);
    float2* sW1 = (float2*)(sR + RH*RH);

    const int b = blockIdx.z;
    const int ox0 = blockIdx.x*TI, oy0 = blockIdx.y*TI;
    const int tid = threadIdx.x;

    // ---- stage weights ----
    {
        const uint4* src = (const uint4*)(Bw_base + ((size_t)(layer*NB + b))*BROWS*32);
        for (int idx = tid; idx < BROWS*4; idx += 256) {
            int row = idx >> 2, j = idx & 3;
            *(uint4*)(sB + row*BSTR + j*8) = src[idx];
        }
    }

    if (C1) {
        for (int p = tid; p < RH*RH; p += 256) {
            int yy = p/RH, xx = p - RH*yy;
            int gy = oy0 + yy - 2, gx = ox0 + xx - 2;
            float v = 0.f;
            if ((unsigned)gy < 256u && (unsigned)gx < 256u)
                v = g_rhat[(size_t)b*GG + gy*256 + gx];
            sR[p] = v;
        }
        if (tid < CH*9) {
            int off = b*(CH*9) + tid;
            sW1[tid] = make_float2(w1r[off], w1i[off]);
        }
        __syncthreads();

        for (int p = tid; p < TH*TH; p += 256) {
            int yy = p/TH, xx = p - TH*yy;
            int gy = oy0 + yy - 1, gx = ox0 + xx - 1;
            uint4* dh = (uint4*)(sX + p*XSTR);
            if ((unsigned)gy < 256u && (unsigned)gx < 256u) {
                float pr[3][3];
#pragma unroll
                for (int t = 0; t < 3; t++)
#pragma unroll
                    for (int s = 0; s < 3; s++)
                        pr[t][s] = sR[(yy+t)*RH + xx+s];
                float ar[16], ai[16];
#pragma unroll
                for (int c = 0; c < 16; c++) { ar[c] = 0.f; ai[c] = 0.f; }
#pragma unroll
                for (int k = 0; k < 9; k++) {
                    int dy = k/3, dx = k - dy*3;
                    float xv = pr[dy][dx];
#pragma unroll
                    for (int c = 0; c < 16; c++) {
                        float2 w = sW1[c*9 + k];
                        ar[c] = fmaf(w.x, xv, ar[c]);
                        ai[c] = fmaf(w.y, xv, ai[c]);
                    }
                }
                u32 h[16];
#pragma unroll
                for (int j = 0; j < 8; j++)
                    h[j] = pk16(ar[2*j]*ASCALE, ar[2*j+1]*ASCALE);
#pragma unroll
                for (int j = 0; j < 8; j++)
                    h[8+j] = pk16(ai[2*j]*ASCALE, ai[2*j+1]*ASCALE);
#pragma unroll
                for (int j = 0; j < 4; j++)
                    dh[j] = make_uint4(h[4*j],h[4*j+1],h[4*j+2],h[4*j+3]);
            } else {
                uint4 z = make_uint4(0,0,0,0);
#pragma unroll
                for (int j = 0; j < 4; j++) dh[j] = z;
            }
        }
    } else {
        for (int p = tid; p < TH*TH; p += 256) {
            int yy = p/TH, xx = p - TH*yy;
            int gy = oy0 + yy - 1, gx = ox0 + xx - 1;
            uint4 vh[4];
            if ((unsigned)gy < 256u && (unsigned)gx < 256u) {
                size_t pb = (((size_t)b*256 + gy)*256 + gx)*32;
                const uint4* ph = (const uint4*)(in + pb);
#pragma unroll
                for (int j = 0; j < 4; j++) vh[j] = ph[j];
            } else {
                uint4 z = make_uint4(0,0,0,0);
#pragma unroll
                for (int j = 0; j < 4; j++) vh[j] = z;
            }
            uint4* dh = (uint4*)(sX + p*XSTR);
#pragma unroll
            for (int j = 0; j < 4; j++) dh[j] = vh[j];
        }
    }
    __syncthreads();

    const int w = tid >> 5, lane = tid & 31;
    const int mrow = ((lane>>3)&1)*8 + (lane&7);
    const int kofs = ((lane>>4)&1)*8;
    const u32 sXB = sptr(sX);
    const u32 sBB = sptr(sB);
    const u32 bLaneOff = ((lane & 7)*BSTR + (lane >> 3)*8) * 2;

    float acc[2][4][4];
#pragma unroll
    for (int mt = 0; mt < 2; mt++)
#pragma unroll
        for (int f = 0; f < 4; f++)
#pragma unroll
            for (int j = 0; j < 4; j++) acc[mt][f][j] = 0.f;

#pragma unroll 1
    for (int tap = 0; tap < 9; tap++) {
        int dy = tap/3, dx = tap - 3*dy;
        u32 bhi[2][4][2], blo[2][4][2];
#pragma unroll
        for (int f = 0; f < 4; f++) {
            u32 r[4];
            ldmat4(r, sBB + ((tap*2+0)*32 + f*8)*BSTR*2 + bLaneOff);
            bhi[0][f][0] = r[0]; bhi[0][f][1] = r[1];
            bhi[1][f][0] = r[2]; bhi[1][f][1] = r[3];
            ldmat4(r, sBB + ((tap*2+1)*32 + f*8)*BSTR*2 + bLaneOff);
            blo[0][f][0] = r[0]; blo[0][f][1] = r[1];
            blo[1][f][0] = r[2]; blo[1][f][1] = r[3];
        }
#pragma unroll
        for (int mt = 0; mt < 2; mt++) {
            int sy = w*2 + mt + dy;
            int sx = mrow + dx;
            u32 off = ((sy*TH + sx)*XSTR + kofs)*2;
#pragma unroll
            for (int k16 = 0; k16 < 2; k16++) {
                u32 a[4];
                ldmat4(a, sXB + off + k16*32);
#pragma unroll
                for (int f = 0; f < 4; f++) mma_f16(acc[mt][f], a, bhi[k16][f]);
#pragma unroll
                for (int f = 0; f < 4; f++) mma_f16(acc[mt][f], a, blo[k16][f]);
            }
        }
    }

    const int rA = lane >> 2;
    const int q  = lane & 3;
    const bool isRe = (q < 2);
#pragma unroll
    for (int mt = 0; mt < 2; mt++) {
        int y = oy0 + w*2 + mt;
#pragma unroll
        for (int half = 0; half < 2; half++) {
            int x = ox0 + rA + half*8;
            size_t pb = (((size_t)b*256 + y)*256 + x)*32;
            if (!WT) {
                u32 h4[4];
#pragma unroll
                for (int f = 0; f < 4; f++)
                    h4[f] = pk16(acc[mt][f][half*2+0], acc[mt][f][half*2+1]);
                *(uint4*)(out + pb + q*8) = make_uint4(h4[0],h4[1],h4[2],h4[3]);
            } else {
                size_t wbase = (size_t)b*16*GG + (size_t)y*256 + x;
                u32 h4[4];
#pragma unroll
                for (int f = 0; f < 4; f++) {
                    float o2[2];
#pragma unroll
                    for (int j = 0; j < 2; j++) {
                        float my = acc[mt][f][half*2+j];
                        float prt = __shfl_xor_sync(0xffffffffu, my, 2);
                        int c = (q & 1)*8 + 2*f + j;
                        float wre = wtr[wbase + (size_t)c*GG];
                        float wim = wti[wbase + (size_t)c*GG];
                        o2[j] = isRe ? (my*wre - prt*wim) : (my*wre + prt*wim);
                    }
                    h4[f] = pk16(o2[0], o2[1]);
                }
                *(uint4*)(out + pb + q*8) = make_uint4(h4[0],h4[1],h4[2],h4[3]);
            }
        }
    }
}

// ---------------- conv 16->1 with adj(w1), undoes ASCALE ----------------
__global__ void __launch_bounds__(256) conv_adj1_kernel(
    const __half* __restrict__ in,
    const float* __restrict__ w1r, const float* __restrict__ w1i)
{
    __shared__ float2 sIn[CH][TH*TH];
    __shared__ float2 sW[CH*9];
    const int b  = blockIdx.z;
    const int ox0 = blockIdx.x*TI, oy0 = blockIdx.y*TI;
    const int tid = threadIdx.x;

    if (tid < CH*9) {
        int ci = tid / 9, k = tid % 9;
        int dy = k/3, dx = k - dy*3;
        int off = (b*CH + ci)*9 + dx*3 + dy;
        sW[tid] = make_float2(w1r[off], -w1i[off]);
    }
    for (int p = tid; p < TH*TH; p += 256) {
        int yy = p/TH, xx = p - TH*yy;
        int gy = oy0 + yy - 1, gx = ox0 + xx - 1;
        float2 vals[16];
        if ((unsigned)gy < 256u && (unsigned)gx < 256u) {
            size_t pb = (((size_t)b*256 + gy)*256 + gx)*32;
            uint4 hv[4];
            const uint4* ph = (const uint4*)(in + pb);
#pragma unroll
            for (int j = 0; j < 4; j++) hv[j] = ph[j];
            const __half* hb = (const __half*)hv;
#pragma unroll
            for (int ci = 0; ci < 16; ci++)
                vals[ci] = make_float2(__half2float(hb[ci]), __half2float(hb[ci+16]));
        } else {
#pragma unroll
            for (int ci = 0; ci < 16; ci++) vals[ci] = make_float2(0.f, 0.f);
        }
#pragma unroll
        for (int ci = 0; ci < 16; ci++)
            sIn[ci][p] = vals[ci];
    }
    __syncthreads();

    const int xx = tid & 15, yy = tid >> 4;
    float ar = 0.f, ai = 0.f;
#pragma unroll 1
    for (int ci = 0; ci < CH; ci++) {
#pragma unroll
        for (int k = 0; k < 9; k++) {
            int dy = k/3, dx = k - dy*3;
            float2 w = sW[ci*9 + k];
            float2 x = sIn[ci][(yy+dy)*TH + xx+dx];
            ar = fmaf(w.x, x.x, fmaf(-w.y, x.y, ar));
            ai = fmaf(w.x, x.y, fmaf( w.y, x.x, ai));
        }
    }
    g_c1[(size_t)b*GG + (size_t)(oy0+yy)*256 + ox0+xx] = make_float2(ar*AINV, ai*AINV);
}

// ---------------- forward fft2 pass A ----------------
__global__ void fft_passA_kernel()
{
    __shared__ float2 sA[8*LSTR], sB[8*LSTR], tw[256];
    const int b = blockIdx.y, tid = threadIdx.x;
    const int line = tid >> 5, lt = tid & 31;
    const int m = blockIdx.x*8 + line;
    const int msrc = (m + 128) & 255;
    const size_t base = (size_t)b*GG + (size_t)msrc*256;

    gen_tw(tw, tid, -1.0f);

    float2* s0 = sA + line*LSTR;
    float2* s1 = sB + line*LSTR;
#pragma unroll
    for (int u = 0; u < 8; u++) {
        int k = lt + 32*u;
        s0[k] = g_c1[base + ((k + 128) & 255)];
    }
    __syncthreads();
    fft256_multi(s0, s1, lt, tw);

    const int mi = tid & 7, qsub = tid >> 3;
    const int m0 = blockIdx.x*8;
#pragma unroll
    for (int chunk = 0; chunk < 8; chunk++) {
        int q = chunk*32 + qsub;
        g_c2[(size_t)b*GG + (size_t)q*256 + m0 + mi] = sA[mi*LSTR + q];
    }
}

// ---------------- forward fft2 pass B ----------------
__global__ void fft_passB_kernel(float* __restrict__ out)
{
    __shared__ float2 sA[8*LSTR], sB[8*LSTR], tw[256];
    const int b = blockIdx.y, tid = threadIdx.x;
    const int line = tid >> 5, lt = tid & 31;
    const int q = blockIdx.x*8 + line;
    const bool live = (q < 127);
    const size_t base = (size_t)b*GG + (size_t)(live ? q : 0)*256;

    gen_tw(tw, tid, -1.0f);

    float2* s0 = sA + line*LSTR;
    float2* s1 = sB + line*LSTR;
#pragma unroll
    for (int u = 0; u < 8; u++) {
        int k = lt + 32*u;
        s0[k] = live ? g_c2[base + k] : make_float2(0.f, 0.f);
    }
    __syncthreads();
    fft256_multi(s0, s1, lt, tw);

    const int qi = tid & 7, psub = tid >> 3;
    const int q0 = blockIdx.x*8;
#pragma unroll
    for (int chunk = 0; chunk < 8; chunk++) {
        int p = chunk*32 + psub;
        int qq = q0 + qi;
        if (p < 127 && qq < 127)
            out[((size_t)b*127 + p)*127 + qq] = sA[qi*LSTR + p].x;
    }
}

// ---------------- launch ----------------
extern "C" void kernel_launch(void* const* d_in, const int* in_sizes, int n_in,
                              void* d_out, int out_size)
{
    (void)in_sizes; (void)n_in; (void)out_size;
    const float* r   = (const float*)d_in[0];
    const float* w1r = (const float*)d_in[1];
    const float* w1i = (const float*)d_in[2];
    const float* w2r = (const float*)d_in[3];
    const float* w2i = (const float*)d_in[4];
    const float* w3r = (const float*)d_in[5];
    const float* w3i = (const float*)d_in[6];
    const float* wtr = (const float*)d_in[7];
    const float* wti = (const float*)d_in[8];
    float* out = (float*)d_out;

    void *pA, *pB, *pBw;
    cudaGetSymbolAddress(&pA, g_A);
    cudaGetSymbolAddress(&pB, g_B);
    cudaGetSymbolAddress(&pBw, g_Bw);
    __half* Abuf = (__half*)pA;
    __half* Bbuf = (__half*)pB;
    __half* Bw   = (__half*)pBw;

    cudaFuncSetAttribute((const void*)conv16_mma<false,true >, cudaFuncAttributeMaxDynamicSharedMemorySize, SMEM_MMA_C1);
    cudaFuncSetAttribute((const void*)conv16_mma<false,false>, cudaFuncAttributeMaxDynamicSharedMemorySize, SMEM_MMA);
    cudaFuncSetAttribute((const void*)conv16_mma<true ,false>, cudaFuncAttributeMaxDynamicSharedMemorySize, SMEM_MMA);

    dim3 gwp(NB, 4);
    wprep_kernel<<<gwp, 256>>>(w2r, w2i, w3r, w3i);

    dim3 gfft(32, NB);
    ifft_passA_kernel<<<gfft, 256>>>(r);
    ifft_passB_kernel<<<gfft, 256>>>();

    dim3 gconv(16, 16, NB);
    conv16_mma<false,true ><<<gconv, 256, SMEM_MMA_C1>>>(nullptr, Bbuf, Bw, 0, nullptr, nullptr, w1r, w1i);
    conv16_mma<true ,false><<<gconv, 256, SMEM_MMA>>>(Bbuf, Abuf, Bw, 1, wtr, wti, nullptr, nullptr);
    conv16_mma<false,false><<<gconv, 256, SMEM_MMA>>>(Abuf, Bbuf, Bw, 2, nullptr, nullptr, nullptr, nullptr);
    conv16_mma<false,false><<<gconv, 256, SMEM_MMA>>>(Bbuf, Abuf, Bw, 3, nullptr, nullptr, nullptr, nullptr);

    dim3 gadj(16, 16, NB);
    conv_adj1_kernel<<<gadj, 256>>>(Abuf, w1r, w1i);

    fft_passA_kernel<<<gfft, 256>>>();
    dim3 gfftB(16, NB);
    fft_passB_kernel<<<gfftB, 256>>>(out);
}

// round 17
// speedup vs baseline: 1.1524x; 1.1524x over previous
#include <cuda_runtime.h>
#include <cuda_fp16.h>
#include <math.h>

#define NB 32
#define CH 16
#define G  256
#define GG (G*G)

#define XSTR 40
#define BSTR 40
#define TIX  16
#define TIY  32
#define THX  18
#define THY  34
#define RHX  20
#define RHY  36
#define XEL2 (THY*THX*XSTR)                        // 24480 fp16
#define BROWS (9*2*32)
#define SMEM_MMA ((XEL2 + BROWS*BSTR)*2)           // 95,040 B
#define SMEM_MMA_C1 (SMEM_MMA + RHY*RHX*4 + CH*9*8)

#define LSTR 258
#define ASCALE 256.0f
#define AINV   (1.0f/256.0f)

typedef unsigned int u32;

// ---------------- scratch ----------------
__device__ float  g_rhat[NB*GG];
__device__ float2 g_c1[NB*GG];
__device__ float2 g_c2[NB*GG];
__device__ __half g_A[(size_t)NB*GG*32];
__device__ __half g_B[(size_t)NB*GG*32];
__device__ __half g_Bw[4*NB*BROWS*32];

// ---------------- helpers ----------------
__device__ __forceinline__ u32 sptr(const void* p) {
    return (u32)__cvta_generic_to_shared(p);
}
__device__ __forceinline__ void ldmat4(u32* r, u32 addr) {
    asm volatile("ldmatrix.sync.aligned.m8n8.x4.shared.b16 {%0,%1,%2,%3}, [%4];"
        : "=r"(r[0]), "=r"(r[1]), "=r"(r[2]), "=r"(r[3]) : "r"(addr));
}
__device__ __forceinline__ void mma_f16(float* d, const u32* a, const u32* b) {
    asm volatile("mma.sync.aligned.m16n8k16.row.col.f32.f16.f16.f32 "
        "{%0,%1,%2,%3}, {%4,%5,%6,%7}, {%8,%9}, {%0,%1,%2,%3};"
        : "+f"(d[0]), "+f"(d[1]), "+f"(d[2]), "+f"(d[3])
        : "r"(a[0]), "r"(a[1]), "r"(a[2]), "r"(a[3]), "r"(b[0]), "r"(b[1]));
}
__device__ __forceinline__ u32 pk16(float a, float b) {
    u32 r;
    asm("cvt.rn.f16x2.f32 %0, %1, %2;" : "=r"(r) : "f"(b), "f"(a));
    return r;
}
__device__ __forceinline__ int Lperm(int n) {
    return ((n & 7) >> 1) * 8 + ((n >> 3) << 1) + (n & 1);
}

// ---------------- twiddle table ----------------
__device__ __forceinline__ void gen_tw(float2* tw, int tid, float dir)
{
    if (tid < 255) {
        int s  = 31 - __clz(tid + 1);
        int jm = tid - ((1 << s) - 1);
        float ang = dir * 3.14159265358979323846f * (float)jm / (float)(1 << s);
        float sn, cs;
        __sincosf(ang, &sn, &cs);
        tw[tid] = make_float2(cs, sn);
    }
}

// ---------------- 256-pt FFT, 8 lines/block ----------------
__device__ __forceinline__ void fft256_multi(float2* s0, float2* s1, int lt, const float2* tw)
{
    float2* src = s0; float2* dst = s1;
#pragma unroll
    for (int s = 0; s < 8; s++) {
        int Ns = 1 << s;
#pragma unroll
        for (int u = 0; u < 4; u++) {
            int j  = lt + 32*u;
            int jm = j & (Ns - 1);
            float2 a = src[j];
            float2 b = src[j + 128];
            float2 w = tw[Ns - 1 + jm];
            float2 bt = make_float2(b.x*w.x - b.y*w.y, b.x*w.y + b.y*w.x);
            int id = ((j >> s) << (s + 1)) | jm;
            dst[id]      = make_float2(a.x + bt.x, a.y + bt.y);
            dst[id + Ns] = make_float2(a.x - bt.x, a.y - bt.y);
        }
        __syncthreads();
        float2* tt = src; src = dst; dst = tt;
    }
}

// ---------------- ifft2 pass A ----------------
__global__ void ifft_passA_kernel(const float* __restrict__ r)
{
    __shared__ float2 sA[8*LSTR], sB[8*LSTR], tw[256];
    const int b = blockIdx.y, tid = threadIdx.x;
    const int line = tid >> 5, lt = tid & 31;
    const int m = blockIdx.x*8 + line;

    gen_tw(tw, tid, +1.0f);

    const bool zrow = (m == 0 || m == 128);
    const float sm = (m < 128) ? 1.f : -1.f;
    const int   im = (m < 128) ? (m - 1) : (255 - m);
    const float* rrow = r + ((size_t)b*127 + (zrow ? 0 : im))*127;

    float2* s0 = sA + line*LSTR;
    float2* s1 = sB + line*LSTR;
#pragma unroll
    for (int u = 0; u < 8; u++) {
        int n = lt + 32*u;
        float v = 0.f;
        if (!zrow && n != 0 && n != 128)
            v = (n < 128) ? rrow[n-1] : -rrow[255-n];
        s0[n] = make_float2(sm * v, 0.f);
    }
    __syncthreads();
    fft256_multi(s0, s1, lt, tw);

    const float sc = 1.0f / 256.0f;
    const int mi = tid & 7, vsub = tid >> 3;
    const int m0 = blockIdx.x*8;
#pragma unroll
    for (int chunk = 0; chunk < 8; chunk++) {
        int v = chunk*32 + vsub;
        float2 val = sA[mi*LSTR + v];
        g_c1[(size_t)b*GG + (size_t)((v+128)&255)*256 + m0 + mi] =
            make_float2(val.x*sc, val.y*sc);
    }
}

// ---------------- ifft2 pass B ----------------
__global__ void ifft_passB_kernel()
{
    __shared__ float2 sA[8*LSTR], sB[8*LSTR], tw[256];
    const int b = blockIdx.y, tid = threadIdx.x;
    const int line = tid >> 5, lt = tid & 31;
    const int vp = blockIdx.x*8 + line;
    const size_t base = (size_t)b*GG + (size_t)vp*256;

    gen_tw(tw, tid, +1.0f);

    float2* s0 = sA + line*LSTR;
    float2* s1 = sB + line*LSTR;
#pragma unroll
    for (int u = 0; u < 8; u++) {
        int n = lt + 32*u;
        s0[n] = g_c1[base + n];
    }
    __syncthreads();
    fft256_multi(s0, s1, lt, tw);

    const float sc = 1.0f / 256.0f;
    const int vi = tid & 7, usub = tid >> 3;
    const int v0 = blockIdx.x*8;
#pragma unroll
    for (int chunk = 0; chunk < 8; chunk++) {
        int uu = chunk*32 + usub;
        g_rhat[(size_t)b*GG + (size_t)((uu+128)&255)*256 + v0 + vi] =
            sA[vi*LSTR + uu].x * sc;
    }
}

// ---------------- weight precompute: fp16 hi/lo, n-permuted ----------------
__global__ void wprep_kernel(const float* __restrict__ w2r, const float* __restrict__ w2i,
                             const float* __restrict__ w3r, const float* __restrict__ w3i)
{
    const int b = blockIdx.x, layer = blockIdx.y, tid = threadIdx.x;
    const float *wr, *wi; bool adj;
    if      (layer == 0) { wr = w2r; wi = w2i; adj = false; }
    else if (layer == 1) { wr = w3r; wi = w3i; adj = false; }
    else if (layer == 2) { wr = w3r; wi = w3i; adj = true;  }
    else                 { wr = w2r; wi = w2i; adj = true;  }
    __half* dst = g_Bw + ((size_t)(layer*NB + b))*BROWS*32;

    for (int idx = tid; idx < 9*32*32; idx += 256) {
        int tap = idx >> 10;
        int n = (idx >> 5) & 31;
        int k = idx & 31;
        int dy = tap/3, dx = tap - 3*dy;
        int cn = Lperm(n);
        int co = cn & 15, ci = k & 15;
        float vr, vi;
        if (!adj) { int off = ((b*CH + co)*CH + ci)*9 + dy*3 + dx; vr = wr[off]; vi = wi[off]; }
        else      { int off = ((b*CH + ci)*CH + co)*9 + dx*3 + dy; vr = wr[off]; vi = -wi[off]; }
        float v = (cn < 16) ? ((k < 16) ? vr : -vi)
                            : ((k < 16) ? vi :  vr);
        __half h = __float2half(v);
        __half l = __float2half(v - __half2float(h));
        dst[((tap*2 + 0)*32 + n)*32 + k] = h;
        dst[((tap*2 + 1)*32 + n)*32 + k] = l;
    }
}

// ---------------- conv16 via mma.sync fp16; 32x16 tile, warp = 4 rows ----------------
template<bool WT, bool C1>
__global__ void __launch_bounds__(256, 2) conv16_mma(
    const __half* __restrict__ in, __half* __restrict__ out,
    const __half* __restrict__ Bw_base, int layer,
    const float* __restrict__ wtr, const float* __restrict__ wti,
    const float* __restrict__ w1r, const float* __restrict__ w1i)
{
    extern __shared__ __half sm[];
    __half* sX = sm;                        // [THY*THX][XSTR] fp16, 32 used
    __half* sB = sm + XEL2;                 // [(tap*2+hl)*32 + n][BSTR]
    float*  sR  = (float*)(sm + XEL2 + BROWS*BSTR);   // [RHY*RHX]
    float2* sW1 = (float2*)(sR + RHY*RHX);

    const int b = blockIdx.z;
    const int ox0 = blockIdx.x*TIX, oy0 = blockIdx.y*TIY;
    const int tid = threadIdx.x;

    // ---- stage weights ----
    {
        const uint4* src = (const uint4*)(Bw_base + ((size_t)(layer*NB + b))*BROWS*32);
        for (int idx = tid; idx < BROWS*4; idx += 256) {
            int row = idx >> 2, j = idx & 3;
            *(uint4*)(sB + row*BSTR + j*8) = src[idx];
        }
    }

    if (C1) {
        for (int p = tid; p < RHY*RHX; p += 256) {
            int yy = p/RHX, xx = p - RHX*yy;
            int gy = oy0 + yy - 2, gx = ox0 + xx - 2;
            float v = 0.f;
            if ((unsigned)gy < 256u && (unsigned)gx < 256u)
                v = g_rhat[(size_t)b*GG + gy*256 + gx];
            sR[p] = v;
        }
        if (tid < CH*9) {
            int off = b*(CH*9) + tid;
            sW1[tid] = make_float2(w1r[off], w1i[off]);
        }
        __syncthreads();

        for (int p = tid; p < THY*THX; p += 256) {
            int yy = p/THX, xx = p - THX*yy;
            int gy = oy0 + yy - 1, gx = ox0 + xx - 1;
            uint4* dh = (uint4*)(sX + p*XSTR);
            if ((unsigned)gy < 256u && (unsigned)gx < 256u) {
                float pr[3][3];
#pragma unroll
                for (int t = 0; t < 3; t++)
#pragma unroll
                    for (int s = 0; s < 3; s++)
                        pr[t][s] = sR[(yy+t)*RHX + xx+s];
                float ar[16], ai[16];
#pragma unroll
                for (int c = 0; c < 16; c++) { ar[c] = 0.f; ai[c] = 0.f; }
#pragma unroll
                for (int k = 0; k < 9; k++) {
                    int dy = k/3, dx = k - dy*3;
                    float xv = pr[dy][dx];
#pragma unroll
                    for (int c = 0; c < 16; c++) {
                        float2 w = sW1[c*9 + k];
                        ar[c] = fmaf(w.x, xv, ar[c]);
                        ai[c] = fmaf(w.y, xv, ai[c]);
                    }
                }
                u32 h[16];
#pragma unroll
                for (int j = 0; j < 8; j++)
                    h[j] = pk16(ar[2*j]*ASCALE, ar[2*j+1]*ASCALE);
#pragma unroll
                for (int j = 0; j < 8; j++)
                    h[8+j] = pk16(ai[2*j]*ASCALE, ai[2*j+1]*ASCALE);
#pragma unroll
                for (int j = 0; j < 4; j++)
                    dh[j] = make_uint4(h[4*j],h[4*j+1],h[4*j+2],h[4*j+3]);
            } else {
                uint4 z = make_uint4(0,0,0,0);
#pragma unroll
                for (int j = 0; j < 4; j++) dh[j] = z;
            }
        }
    } else {
        for (int p = tid; p < THY*THX; p += 256) {
            int yy = p/THX, xx = p - THX*yy;
            int gy = oy0 + yy - 1, gx = ox0 + xx - 1;
            uint4 vh[4];
            if ((unsigned)gy < 256u && (unsigned)gx < 256u) {
                size_t pb = (((size_t)b*256 + gy)*256 + gx)*32;
                const uint4* ph = (const uint4*)(in + pb);
#pragma unroll
                for (int j = 0; j < 4; j++) vh[j] = ph[j];
            } else {
                uint4 z = make_uint4(0,0,0,0);
#pragma unroll
                for (int j = 0; j < 4; j++) vh[j] = z;
            }
            uint4* dh = (uint4*)(sX + p*XSTR);
#pragma unroll
            for (int j = 0; j < 4; j++) dh[j] = vh[j];
        }
    }
    __syncthreads();

    const int w = tid >> 5, lane = tid & 31;
    const int mrow = ((lane>>3)&1)*8 + (lane&7);
    const int kofs = ((lane>>4)&1)*8;
    const u32 sXB = sptr(sX);
    const u32 sBB = sptr(sB);
    const u32 bLaneOff = ((lane & 7)*BSTR + (lane >> 3)*8) * 2;

    float acc[4][4][4];
#pragma unroll
    for (int mt = 0; mt < 4; mt++)
#pragma unroll
        for (int f = 0; f < 4; f++)
#pragma unroll
            for (int j = 0; j < 4; j++) acc[mt][f][j] = 0.f;

#pragma unroll 1
    for (int tap = 0; tap < 9; tap++) {
        int dy = tap/3, dx = tap - 3*dy;
        u32 bhi[2][4][2], blo[2][4][2];
#pragma unroll
        for (int f = 0; f < 4; f++) {
            u32 r[4];
            ldmat4(r, sBB + ((tap*2+0)*32 + f*8)*BSTR*2 + bLaneOff);
            bhi[0][f][0] = r[0]; bhi[0][f][1] = r[1];
            bhi[1][f][0] = r[2]; bhi[1][f][1] = r[3];
            ldmat4(r, sBB + ((tap*2+1)*32 + f*8)*BSTR*2 + bLaneOff);
            blo[0][f][0] = r[0]; blo[0][f][1] = r[1];
            blo[1][f][0] = r[2]; blo[1][f][1] = r[3];
        }
#pragma unroll
        for (int mt = 0; mt < 4; mt++) {
            int sy = w*4 + mt + dy;
            int sx = mrow + dx;
            u32 off = ((sy*THX + sx)*XSTR + kofs)*2;
#pragma unroll
            for (int k16 = 0; k16 < 2; k16++) {
                u32 a[4];
                ldmat4(a, sXB + off + k16*32);
#pragma unroll
                for (int f = 0; f < 4; f++) mma_f16(acc[mt][f], a, bhi[k16][f]);
#pragma unroll
                for (int f = 0; f < 4; f++) mma_f16(acc[mt][f], a, blo[k16][f]);
            }
        }
    }

    const int rA = lane >> 2;
    const int q  = lane & 3;
    const bool isRe = (q < 2);
#pragma unroll
    for (int mt = 0; mt < 4; mt++) {
        int y = oy0 + w*4 + mt;
#pragma unroll
        for (int half = 0; half < 2; half++) {
            int x = ox0 + rA + half*8;
            size_t pb = (((size_t)b*256 + y)*256 + x)*32;
            if (!WT) {
                u32 h4[4];
#pragma unroll
                for (int f = 0; f < 4; f++)
                    h4[f] = pk16(acc[mt][f][half*2+0], acc[mt][f][half*2+1]);
                *(uint4*)(out + pb + q*8) = make_uint4(h4[0],h4[1],h4[2],h4[3]);
            } else {
                size_t wbase = (size_t)b*16*GG + (size_t)y*256 + x;
                u32 h4[4];
#pragma unroll
                for (int f = 0; f < 4; f++) {
                    float o2[2];
#pragma unroll
                    for (int j = 0; j < 2; j++) {
                        float my = acc[mt][f][half*2+j];
                        float prt = __shfl_xor_sync(0xffffffffu, my, 2);
                        int c = (q & 1)*8 + 2*f + j;
                        float wre = wtr[wbase + (size_t)c*GG];
                        float wim = wti[wbase + (size_t)c*GG];
                        o2[j] = isRe ? (my*wre - prt*wim) : (my*wre + prt*wim);
                    }
                    h4[f] = pk16(o2[0], o2[1]);
                }
                *(uint4*)(out + pb + q*8) = make_uint4(h4[0],h4[1],h4[2],h4[3]);
            }
        }
    }
}

// ---------------- conv 16->1 with adj(w1), undoes ASCALE ----------------
#define ATH 18
__global__ void __launch_bounds__(256) conv_adj1_kernel(
    const __half* __restrict__ in,
    const float* __restrict__ w1r, const float* __restrict__ w1i)
{
    __shared__ float2 sIn[CH][ATH*ATH];
    __shared__ float2 sW[CH*9];
    const int b  = blockIdx.z;
    const int ox0 = blockIdx.x*16, oy0 = blockIdx.y*16;
    const int tid = threadIdx.x;

    if (tid < CH*9) {
        int ci = tid / 9, k = tid % 9;
        int dy = k/3, dx = k - dy*3;
        int off = (b*CH + ci)*9 + dx*3 + dy;
        sW[tid] = make_float2(w1r[off], -w1i[off]);
    }
    for (int p = tid; p < ATH*ATH; p += 256) {
        int yy = p/ATH, xx = p - ATH*yy;
        int gy = oy0 + yy - 1, gx = ox0 + xx - 1;
        float2 vals[16];
        if ((unsigned)gy < 256u && (unsigned)gx < 256u) {
            size_t pb = (((size_t)b*256 + gy)*256 + gx)*32;
            uint4 hv[4];
            const uint4* ph = (const uint4*)(in + pb);
#pragma unroll
            for (int j = 0; j < 4; j++) hv[j] = ph[j];
            const __half* hb = (const __half*)hv;
#pragma unroll
            for (int ci = 0; ci < 16; ci++)
                vals[ci] = make_float2(__half2float(hb[ci]), __half2float(hb[ci+16]));
        } else {
#pragma unroll
            for (int ci = 0; ci < 16; ci++) vals[ci] = make_float2(0.f, 0.f);
        }
#pragma unroll
        for (int ci = 0; ci < 16; ci++)
            sIn[ci][p] = vals[ci];
    }
    __syncthreads();

    const int xx = tid & 15, yy = tid >> 4;
    float ar = 0.f, ai = 0.f;
#pragma unroll 1
    for (int ci = 0; ci < CH; ci++) {
#pragma unroll
        for (int k = 0; k < 9; k++) {
            int dy = k/3, dx = k - dy*3;
            float2 w = sW[ci*9 + k];
            float2 x = sIn[ci][(yy+dy)*ATH + xx+dx];
            ar = fmaf(w.x, x.x, fmaf(-w.y, x.y, ar));
            ai = fmaf(w.x, x.y, fmaf( w.y, x.x, ai));
        }
    }
    g_c1[(size_t)b*GG + (size_t)(oy0+yy)*256 + ox0+xx] = make_float2(ar*AINV, ai*AINV);
}

// ---------------- forward fft2 pass A ----------------
__global__ void fft_passA_kernel()
{
    __shared__ float2 sA[8*LSTR], sB[8*LSTR], tw[256];
    const int b = blockIdx.y, tid = threadIdx.x;
    const int line = tid >> 5, lt = tid & 31;
    const int m = blockIdx.x*8 + line;
    const int msrc = (m + 128) & 255;
    const size_t base = (size_t)b*GG + (size_t)msrc*256;

    gen_tw(tw, tid, -1.0f);

    float2* s0 = sA + line*LSTR;
    float2* s1 = sB + line*LSTR;
#pragma unroll
    for (int u = 0; u < 8; u++) {
        int k = lt + 32*u;
        s0[k] = g_c1[base + ((k + 128) & 255)];
    }
    __syncthreads();
    fft256_multi(s0, s1, lt, tw);

    const int mi = tid & 7, qsub = tid >> 3;
    const int m0 = blockIdx.x*8;
#pragma unroll
    for (int chunk = 0; chunk < 8; chunk++) {
        int q = chunk*32 + qsub;
        g_c2[(size_t)b*GG + (size_t)q*256 + m0 + mi] = sA[mi*LSTR + q];
    }
}

// ---------------- forward fft2 pass B ----------------
__global__ void fft_passB_kernel(float* __restrict__ out)
{
    __shared__ float2 sA[8*LSTR], sB[8*LSTR], tw[256];
    const int b = blockIdx.y, tid = threadIdx.x;
    const int line = tid >> 5, lt = tid & 31;
    const int q = blockIdx.x*8 + line;
    const bool live = (q < 127);
    const size_t base = (size_t)b*GG + (size_t)(live ? q : 0)*256;

    gen_tw(tw, tid, -1.0f);

    float2* s0 = sA + line*LSTR;
    float2* s1 = sB + line*LSTR;
#pragma unroll
    for (int u = 0; u < 8; u++) {
        int k = lt + 32*u;
        s0[k] = live ? g_c2[base + k] : make_float2(0.f, 0.f);
    }
    __syncthreads();
    fft256_multi(s0, s1, lt, tw);

    const int qi = tid & 7, psub = tid >> 3;
    const int q0 = blockIdx.x*8;
#pragma unroll
    for (int chunk = 0; chunk < 8; chunk++) {
        int p = chunk*32 + psub;
        int qq = q0 + qi;
        if (p < 127 && qq < 127)
            out[((size_t)b*127 + p)*127 + qq] = sA[qi*LSTR + p].x;
    }
}

// ---------------- launch ----------------
extern "C" void kernel_launch(void* const* d_in, const int* in_sizes, int n_in,
                              void* d_out, int out_size)
{
    (void)in_sizes; (void)n_in; (void)out_size;
    const float* r   = (const float*)d_in[0];
    const float* w1r = (const float*)d_in[1];
    const float* w1i = (const float*)d_in[2];
    const float* w2r = (const float*)d_in[3];
    const float* w2i = (const float*)d_in[4];
    const float* w3r = (const float*)d_in[5];
    const float* w3i = (const float*)d_in[6];
    const float* wtr = (const float*)d_in[7];
    const float* wti = (const float*)d_in[8];
    float* out = (float*)d_out;

    void *pA, *pB, *pBw;
    cudaGetSymbolAddress(&pA, g_A);
    cudaGetSymbolAddress(&pB, g_B);
    cudaGetSymbolAddress(&pBw, g_Bw);
    __half* Abuf = (__half*)pA;
    __half* Bbuf = (__half*)pB;
    __half* Bw   = (__half*)pBw;

    cudaFuncSetAttribute((const void*)conv16_mma<false,true >, cudaFuncAttributeMaxDynamicSharedMemorySize, SMEM_MMA_C1);
    cudaFuncSetAttribute((const void*)conv16_mma<false,false>, cudaFuncAttributeMaxDynamicSharedMemorySize, SMEM_MMA);
    cudaFuncSetAttribute((const void*)conv16_mma<true ,false>, cudaFuncAttributeMaxDynamicSharedMemorySize, SMEM_MMA);

    dim3 gwp(NB, 4);
    wprep_kernel<<<gwp, 256>>>(w2r, w2i, w3r, w3i);

    dim3 gfft(32, NB);
    ifft_passA_kernel<<<gfft, 256>>>(r);
    ifft_passB_kernel<<<gfft, 256>>>();

    dim3 gconv(16, 8, NB);
    conv16_mma<false,true ><<<gconv, 256, SMEM_MMA_C1>>>(nullptr, Bbuf, Bw, 0, nullptr, nullptr, w1r, w1i);
    conv16_mma<true ,false><<<gconv, 256, SMEM_MMA>>>(Bbuf, Abuf, Bw, 1, wtr, wti, nullptr, nullptr);
    conv16_mma<false,false><<<gconv, 256, SMEM_MMA>>>(Abuf, Bbuf, Bw, 2, nullptr, nullptr, nullptr, nullptr);
    conv16_mma<false,false><<<gconv, 256, SMEM_MMA>>>(Bbuf, Abuf, Bw, 3, nullptr, nullptr, nullptr, nullptr);

    dim3 gadj(16, 16, NB);
    conv_adj1_kernel<<<gadj, 256>>>(Abuf, w1r, w1i);

    fft_passA_kernel<<<gfft, 256>>>();
    dim3 gfftB(16, NB);
    fft_passB_kernel<<<gfftB, 256>>>(out);
}